// round 4
// baseline (speedup 1.0000x reference)
#include <cuda_runtime.h>
#include <cstdint>
#include <cmath>

// Problem constants
#define BATCH    16
#define NPTS     1024
#define EDIM     128
#define KVS      259      // 2*E + 3 floats per kv row
#define TILE_N   64       // n rows per block
#define TILE_M   128      // m cols per smem tile
#define NTHREADS 128      // 8 ty (8 n each) x 16 tx (8 m each)

// Shared memory layout (floats). Padded strides keep 16B alignment (stride%4==0)
// while limiting fill-phase bank conflicts to 4-way.
#define KS_STRIDE 68
#define VS_STRIDE 132
#define KS_OFF 0
#define VS_OFF (EDIM * KS_STRIDE)                 // 8704
#define PM_OFF (VS_OFF + EDIM * VS_STRIDE)       // 25600
#define SMEM_FLOATS (PM_OFF + 3 * TILE_M)        // 25984
#define SMEM_BYTES  (SMEM_FLOATS * 4)            // 103936 B -> 2 blocks/SM

// ---------------- packed f32x2 helpers (sm_103a) ----------------
__device__ __forceinline__ unsigned long long ffma2(unsigned long long a,
                                                    unsigned long long b,
                                                    unsigned long long c) {
    unsigned long long d;
    asm("fma.rn.f32x2 %0, %1, %2, %3;" : "=l"(d) : "l"(a), "l"(b), "l"(c));
    return d;
}
__device__ __forceinline__ unsigned long long dup2(float x) {
    unsigned long long d;
    asm("mov.b64 %0, {%1, %1};" : "=l"(d) : "f"(x));
    return d;
}
__device__ __forceinline__ void unpack2(unsigned long long v, float &lo, float &hi) {
    asm("mov.b64 {%0, %1}, %2;" : "=f"(lo), "=f"(hi) : "l"(v));
}

// Per-pair geometric epilogue.
// Reference computes  s * d / (||d|| + 1e-8).  For ||d|| >> 1e-8 this equals
// s * d * rsqrt(d2) to within eps/||d|| (<=1e-4 relative even at ||d||=1e-4,
// further diluted by the 1024-term sum).  d2 == 0 happens only at n == m,
// where the reference contribution is exactly 0 -> select 0 there (also
// avoids rsqrt(0)=inf -> inf*0=NaN).
__device__ __forceinline__ void epil(float s,
                                     float pnx_, float pny_, float pnz_,
                                     float pmx_, float pmy_, float pmz_,
                                     float &ax_, float &ay_, float &az_) {
    float dx = pnx_ - pmx_;
    float dy = pny_ - pmy_;
    float dz = pnz_ - pmz_;
    float d2 = fmaf(dx, dx, fmaf(dy, dy, dz * dz));
    float rinv;
    asm("rsqrt.approx.f32 %0, %1;" : "=f"(rinv) : "f"(d2));
    float w = (d2 > 0.0f) ? s * rinv : 0.0f;
    ax_ = fmaf(w, dx, ax_);
    ay_ = fmaf(w, dy, ay_);
    az_ = fmaf(w, dz, az_);
}

__global__ void __launch_bounds__(NTHREADS, 2)
actor_kernel(const float* __restrict__ kv,
             const float* __restrict__ pos,
             float* __restrict__ out)
{
    extern __shared__ float sm[];
    const uint32_t smb = (uint32_t)__cvta_generic_to_shared(sm);

    const int tid = threadIdx.x;
    const int tx  = tid & 15;   // m direction, 8 m each
    const int ty  = tid >> 4;   // n direction, 8 n each
    const int b   = blockIdx.x >> 4;
    const int n0  = (blockIdx.x & 15) * TILE_N;

    const float* kvb  = kv  + (size_t)b * NPTS * KVS;
    const float* posb = pos + (size_t)b * NPTS * 3;

    // ---- fill ksT[e][nn] once (e = tid since NTHREADS == EDIM) ----
    #pragma unroll 4
    for (int i = 0; i < TILE_N; i++)
        sm[KS_OFF + tid * KS_STRIDE + i] = kvb[(size_t)(n0 + i) * KVS + tid];

    // ---- this thread's 8 n-row positions (registers, whole kernel) ----
    float pnx[8], pny[8], pnz[8];
    #pragma unroll
    for (int i = 0; i < 8; i++) {
        int n = n0 + ty * 8 + i;
        pnx[i] = posb[(size_t)n * 3 + 0];
        pny[i] = posb[(size_t)n * 3 + 1];
        pnz[i] = posb[(size_t)n * 3 + 2];
    }

    float ax[8], ay[8], az[8];
    #pragma unroll
    for (int i = 0; i < 8; i++) { ax[i] = 0.f; ay[i] = 0.f; az[i] = 0.f; }

    const uint32_t ks_base = smb + (uint32_t)(KS_OFF * 4) + (uint32_t)ty * 32u;
    const uint32_t vs_base = smb + (uint32_t)(VS_OFF * 4) + (uint32_t)tx * 32u;

    for (int m0 = 0; m0 < NPTS; m0 += TILE_M) {
        __syncthreads();   // previous tile's readers done before refill

        // ---- fill vsT[e][mm] (e = tid) : coalesced global reads ----
        #pragma unroll 4
        for (int i = 0; i < TILE_M; i++)
            sm[VS_OFF + tid * VS_STRIDE + i] =
                kvb[(size_t)(m0 + i) * KVS + EDIM + tid];

        // ---- fill pm[d][mm] ----
        for (int i = tid; i < 3 * TILE_M; i += NTHREADS) {
            int d  = i >> 7;
            int mm = i & 127;
            sm[PM_OFF + d * TILE_M + mm] = posb[(size_t)(m0 + mm) * 3 + d];
        }
        __syncthreads();

        // ---- 8x8 register-tile GEMM over K=128, n packed in f32x2 pairs ----
        unsigned long long acc2[4][8];
        #pragma unroll
        for (int p = 0; p < 4; p++)
            #pragma unroll
            for (int j = 0; j < 8; j++) acc2[p][j] = 0ull;

        #pragma unroll 4
        for (int k = 0; k < EDIM; k++) {
            unsigned long long a[4];
            const uint32_t ka = ks_base + (uint32_t)(k * (KS_STRIDE * 4));
            const uint32_t kb = vs_base + (uint32_t)(k * (VS_STRIDE * 4));
            asm volatile("ld.shared.v2.b64 {%0, %1}, [%2];"
                         : "=l"(a[0]), "=l"(a[1]) : "r"(ka));
            asm volatile("ld.shared.v2.b64 {%0, %1}, [%2];"
                         : "=l"(a[2]), "=l"(a[3]) : "r"(ka + 16u));
            float b0, b1, b2, b3, b4, b5, b6, b7;
            asm volatile("ld.shared.v4.f32 {%0, %1, %2, %3}, [%4];"
                         : "=f"(b0), "=f"(b1), "=f"(b2), "=f"(b3) : "r"(kb));
            asm volatile("ld.shared.v4.f32 {%0, %1, %2, %3}, [%4];"
                         : "=f"(b4), "=f"(b5), "=f"(b6), "=f"(b7) : "r"(kb + 16u));
            unsigned long long bd[8];
            bd[0] = dup2(b0); bd[1] = dup2(b1); bd[2] = dup2(b2); bd[3] = dup2(b3);
            bd[4] = dup2(b4); bd[5] = dup2(b5); bd[6] = dup2(b6); bd[7] = dup2(b7);
            #pragma unroll
            for (int p = 0; p < 4; p++)
                #pragma unroll
                for (int j = 0; j < 8; j++)
                    acc2[p][j] = ffma2(a[p], bd[j], acc2[p][j]);
        }

        // ---- fused epilogue for this m-tile ----
        float pmx[8], pmy[8], pmz[8];
        #pragma unroll
        for (int j = 0; j < 8; j++) {
            int mm = tx * 8 + j;
            pmx[j] = sm[PM_OFF + mm];
            pmy[j] = sm[PM_OFF + TILE_M + mm];
            pmz[j] = sm[PM_OFF + 2 * TILE_M + mm];
        }
        #pragma unroll
        for (int p = 0; p < 4; p++) {
            #pragma unroll
            for (int j = 0; j < 8; j++) {
                float s0, s1;
                unpack2(acc2[p][j], s0, s1);
                const int nl = 2 * p, nh = 2 * p + 1;
                epil(s0, pnx[nl], pny[nl], pnz[nl], pmx[j], pmy[j], pmz[j],
                     ax[nl], ay[nl], az[nl]);
                epil(s1, pnx[nh], pny[nh], pnz[nh], pmx[j], pmy[j], pmz[j],
                     ax[nh], ay[nh], az[nh]);
            }
        }
    }

    // ---- reduce over the 16 tx lanes (xor masks < 16 stay in the ty half) ----
    #pragma unroll
    for (int i = 0; i < 8; i++) {
        #pragma unroll
        for (int msk = 8; msk > 0; msk >>= 1) {
            ax[i] += __shfl_xor_sync(0xffffffffu, ax[i], msk);
            ay[i] += __shfl_xor_sync(0xffffffffu, ay[i], msk);
            az[i] += __shfl_xor_sync(0xffffffffu, az[i], msk);
        }
    }

    if (tx == 0) {
        const float invsq = 0.08838834764831845f;  // 1/sqrt(128), folded here
        #pragma unroll
        for (int i = 0; i < 8; i++) {
            int n = n0 + ty * 8 + i;
            float* o = out + ((size_t)b * NPTS + n) * 3;
            o[0] = 0.01f * tanhf(ax[i] * invsq);
            o[1] = 0.01f * tanhf(ay[i] * invsq);
            o[2] = 0.01f * tanhf(az[i] * invsq);
        }
    }
}

extern "C" void kernel_launch(void* const* d_in, const int* in_sizes, int n_in,
                              void* d_out, int out_size)
{
    const float* kv  = (const float*)d_in[0];
    const float* pos = (const float*)d_in[1];
    // Defensive: kv is the big tensor (B*N*259), positions the small one (B*N*3)
    if (n_in >= 2 && in_sizes[0] < in_sizes[1]) {
        const float* t = kv; kv = pos; pos = t;
    }
    float* out = (float*)d_out;

    cudaFuncSetAttribute(actor_kernel,
                         cudaFuncAttributeMaxDynamicSharedMemorySize, SMEM_BYTES);

    dim3 grid(BATCH * (NPTS / TILE_N));  // 256 blocks, single wave at 2/SM
    actor_kernel<<<grid, NTHREADS, SMEM_BYTES>>>(kv, pos, out);
}